// round 12
// baseline (speedup 1.0000x reference)
#include <cuda_runtime.h>
#include <cuda_fp16.h>
#include <cstdint>

#define BN_TOT 2048
#define M_DIM  256
#define CIN    64
#define CMID   256
#define COUT   256
#define W2P    320
#define AP     72          // fp16 smem pitch (144B rows), verified round 4
#define STP    136         // epilogue stage pitch in floats (136%32==8 -> conflict-free STS)

// device scratch (zero-alloc rule)
__device__ float  g_zmax[BN_TOT * CMID];   // 2 MB, final max(+bias)
__device__ float  g_v[BN_TOT * COUT];      // 2 MB
__device__ __half g_w2bT[256 * 256];       // w2 cols 64..319 TRANSPOSED [d][o], fp16

// ---------------- PTX helpers ----------------
__device__ __forceinline__ unsigned smem_u32(const void* p) {
    return (unsigned)__cvta_generic_to_shared(p);
}
__device__ __forceinline__ void ldm4(unsigned r[4], unsigned addr) {
    asm volatile("ldmatrix.sync.aligned.m8n8.x4.shared.b16 {%0,%1,%2,%3}, [%4];"
                 : "=r"(r[0]), "=r"(r[1]), "=r"(r[2]), "=r"(r[3]) : "r"(addr));
}
__device__ __forceinline__ void mma_f16(float c[4], const unsigned a[4], const unsigned b[2]) {
    asm volatile("mma.sync.aligned.m16n8k16.row.col.f32.f16.f16.f32 "
                 "{%0,%1,%2,%3}, {%4,%5,%6,%7}, {%8,%9}, {%0,%1,%2,%3};"
                 : "+f"(c[0]), "+f"(c[1]), "+f"(c[2]), "+f"(c[3])
                 : "r"(a[0]), "r"(a[1]), "r"(a[2]), "r"(a[3]), "r"(b[0]), "r"(b[1]));
}

// ---------------------------------------------------------------------------
// Round-4 verified loader: 128 rows x 64 fp32 -> fp16 smem pitch AP
// ---------------------------------------------------------------------------
__device__ __forceinline__ void load_conv(__half* sm, const float* __restrict__ g,
                                          int row0, int pitch, int tid) {
#pragma unroll
    for (int it = 0; it < 4; it++) {
        int idx = it * 256 + tid;          // 0..1023
        int row = idx >> 3, q = idx & 7;
        const float* p = g + (size_t)(row0 + row) * pitch + q * 8;
        float4 v0 = *(const float4*)p;
        float4 v1 = *(const float4*)(p + 4);
        __half2 h0 = __halves2half2(__float2half_rn(v0.x), __float2half_rn(v0.y));
        __half2 h1 = __halves2half2(__float2half_rn(v0.z), __float2half_rn(v0.w));
        __half2 h2 = __halves2half2(__float2half_rn(v1.x), __float2half_rn(v1.y));
        __half2 h3 = __halves2half2(__float2half_rn(v1.z), __float2half_rn(v1.w));
        uint4 u;
        u.x = *(unsigned*)&h0; u.y = *(unsigned*)&h1;
        u.z = *(unsigned*)&h2; u.w = *(unsigned*)&h3;
        *(uint4*)(sm + row * AP + q * 8) = u;
    }
}

// ---------------------------------------------------------------------------
// Round-4 verified MMA core: 128x128x64, warp tile 32m x 64n
// ---------------------------------------------------------------------------
__device__ __forceinline__ void mma_core(float acc[2][8][4],
                                         const __half* sA, const __half* sB,
                                         int warp_m, int warp_n, int lane) {
    const int lrow = lane & 15, lkh = (lane >> 4) * 8;
#pragma unroll
    for (int ks = 0; ks < 64; ks += 16) {
        unsigned af[2][4];
#pragma unroll
        for (int mi = 0; mi < 2; mi++)
            ldm4(af[mi], smem_u32(sA + (warp_m * 32 + mi * 16 + lrow) * AP + ks + lkh));
        unsigned bf[8][2];
#pragma unroll
        for (int np = 0; np < 4; np++) {
            unsigned t[4];
            ldm4(t, smem_u32(sB + (warp_n * 64 + np * 16 + lrow) * AP + ks + lkh));
            bf[2*np][0]   = t[0]; bf[2*np+1][0] = t[1];
            bf[2*np][1]   = t[2]; bf[2*np+1][1] = t[3];
        }
#pragma unroll
        for (int mi = 0; mi < 2; mi++)
#pragma unroll
            for (int ni = 0; ni < 8; ni++)
                mma_f16(acc[mi][ni], af[mi], bf[ni]);
    }
}

// ---------------------------------------------------------------------------
// K1 (round-4 core + folded w2b prep): grid(2 dt, BN). z = x @ w1^T,
// max over 256 m, + bias -> g_zmax.
// ---------------------------------------------------------------------------
__global__ void __launch_bounds__(256)
k1_mma_max(const float* __restrict__ x, const float* __restrict__ w1,
           const float* __restrict__ b1, const float* __restrict__ w2)
{
    __shared__ __align__(16) __half sA[128 * AP];
    __shared__ __align__(16) __half sB[128 * AP];
    __shared__ float smax[4][128];

    const int tid = threadIdx.x;
    const int lane = tid & 31, w = tid >> 5;
    const int warp_m = w >> 1, warp_n = w & 1;
    const int dt = blockIdx.x, bn = blockIdx.y;

    smax[tid >> 7][tid & 127] = -3.4e38f;
    smax[2 + (tid >> 7)][tid & 127] = -3.4e38f;

    load_conv(sB, w1, dt * 128, CIN, tid);

    // folded prep: first 64 bn-CTAs of dt==0 build g_w2bT (K2 runs after K1)
    if (dt == 0 && bn < 64) {
#pragma unroll
        for (int it = 0; it < 4; it++) {
            int j = bn * 1024 + it * 256 + tid;   // 0..65535
            int o = j & 255, d = j >> 8;
            g_w2bT[d * 256 + o] = __float2half_rn(w2[(size_t)o * W2P + CIN + d]);
        }
    }

#pragma unroll
    for (int mt = 0; mt < 2; mt++) {
        __syncthreads();
        load_conv(sA, x, bn * 256 + mt * 128, CIN, tid);
        __syncthreads();

        float acc[2][8][4];
#pragma unroll
        for (int mi = 0; mi < 2; mi++)
#pragma unroll
            for (int ni = 0; ni < 8; ni++)
#pragma unroll
                for (int c = 0; c < 4; c++) acc[mi][ni][c] = 0.f;

        mma_core(acc, sA, sB, warp_m, warp_n, lane);

#pragma unroll
        for (int ni = 0; ni < 8; ni++) {
            float m0 = fmaxf(fmaxf(acc[0][ni][0], acc[0][ni][2]),
                             fmaxf(acc[1][ni][0], acc[1][ni][2]));
            float m1 = fmaxf(fmaxf(acc[0][ni][1], acc[0][ni][3]),
                             fmaxf(acc[1][ni][1], acc[1][ni][3]));
#pragma unroll
            for (int off = 4; off < 32; off <<= 1) {
                m0 = fmaxf(m0, __shfl_xor_sync(0xffffffffu, m0, off));
                m1 = fmaxf(m1, __shfl_xor_sync(0xffffffffu, m1, off));
            }
            if (lane < 4) {
                int col = warp_n * 64 + ni * 8 + lane * 2;
                smax[warp_m][col]     = fmaxf(smax[warp_m][col], m0);
                smax[warp_m][col + 1] = fmaxf(smax[warp_m][col + 1], m1);
            }
        }
    }

    __syncthreads();
    if (tid < 128) {
        float m = fmaxf(fmaxf(smax[0][tid], smax[1][tid]),
                        fmaxf(smax[2][tid], smax[3][tid]));
        g_zmax[(size_t)bn * CMID + dt * 128 + tid] = m + b1[dt * 128 + tid];
    }
}

// ---------------------------------------------------------------------------
// K2 (round-9 verified): grid(BN/4). 4 bn rows x 256 outputs per CTA.
// ---------------------------------------------------------------------------
__global__ void __launch_bounds__(256)
k2_v()
{
    __shared__ float zs[4][256];
    const int tid = threadIdx.x;
    const int bn0 = blockIdx.x * 4;

#pragma unroll
    for (int i = 0; i < 4; i++)
        zs[i][tid] = g_zmax[(size_t)(bn0 + i) * CMID + tid];
    __syncthreads();

    float a0 = 0.f, a1 = 0.f, a2 = 0.f, a3 = 0.f;
    const __half* wp = g_w2bT + tid;
#pragma unroll 4
    for (int d = 0; d < 256; d += 2) {
        float w0 = __half2float(wp[(size_t)d * 256]);
        float w1v = __half2float(wp[(size_t)(d + 1) * 256]);
        float2 z0 = *(const float2*)&zs[0][d];
        float2 z1 = *(const float2*)&zs[1][d];
        float2 z2 = *(const float2*)&zs[2][d];
        float2 z3 = *(const float2*)&zs[3][d];
        a0 = fmaf(z0.x, w0, a0); a0 = fmaf(z0.y, w1v, a0);
        a1 = fmaf(z1.x, w0, a1); a1 = fmaf(z1.y, w1v, a1);
        a2 = fmaf(z2.x, w0, a2); a2 = fmaf(z2.y, w1v, a2);
        a3 = fmaf(z3.x, w0, a3); a3 = fmaf(z3.y, w1v, a3);
    }
    g_v[(size_t)(bn0 + 0) * COUT + tid] = a0;
    g_v[(size_t)(bn0 + 1) * COUT + tid] = a1;
    g_v[(size_t)(bn0 + 2) * COUT + tid] = a2;
    g_v[(size_t)(bn0 + 3) * COUT + tid] = a3;
}

// ---------------------------------------------------------------------------
// K3: grid(2 nt, BN). out = x @ w2a^T + v, 2 row phases.
// NEW: epilogue staged through smem (sA region, dead post-MMA) for
// fully-coalesced STG.128 (4 lines/instr instead of 8).
// ---------------------------------------------------------------------------
__global__ void __launch_bounds__(256)
k3_mma_out(const float* __restrict__ x, const float* __restrict__ w2,
           float* __restrict__ out)
{
    __shared__ __align__(16) __half sA[128 * AP];   // 18432B; also epilogue stage
    __shared__ __align__(16) __half sB[128 * AP];
    __shared__ float sv[128];

    const int tid = threadIdx.x;
    const int lane = tid & 31, w = tid >> 5;
    const int warp_m = w >> 1, warp_n = w & 1;
    const int nt = blockIdx.x, bn = blockIdx.y;

    if (tid < 128) sv[tid] = g_v[(size_t)bn * COUT + nt * 128 + tid];

    load_conv(sB, w2, nt * 128, W2P, tid);   // w2a = first 64 cols of pitch-320 rows

    float* stage = (float*)sA;               // 32 rows x STP floats = 17408B <= 18432B
    const int r_in = lane >> 2;              // 0..7
    const int cgrp = lane & 3;               // 0..3

#pragma unroll
    for (int rt = 0; rt < 2; rt++) {
        const int r0 = bn * 256 + rt * 128;
        __syncthreads();                     // stage reads (prev phase) done
        load_conv(sA, x, r0, CIN, tid);
        __syncthreads();

        float acc[2][8][4];
#pragma unroll
        for (int mi = 0; mi < 2; mi++)
#pragma unroll
            for (int ni = 0; ni < 8; ni++)
#pragma unroll
                for (int c = 0; c < 4; c++) acc[mi][ni][c] = 0.f;

        mma_core(acc, sA, sB, warp_m, warp_n, lane);
        __syncthreads();                     // all sA ldmatrix reads done

        // staged epilogue: 4 rounds of (32 rows x 128 cols)
#pragma unroll
        for (int mi = 0; mi < 2; mi++) {
#pragma unroll
            for (int h = 0; h < 2; h++) {
                // STS: warp writes its 8 rows x 64 cols (+v add)
                {
                    int R = warp_m * 8 + r_in;
                    float* srow = stage + R * STP + warp_n * 64 + cgrp * 2;
#pragma unroll
                    for (int ni = 0; ni < 8; ni++) {
                        float2 vv = *(const float2*)(sv + warp_n * 64 + ni * 8 + cgrp * 2);
                        float2 st;
                        st.x = acc[mi][ni][2 * h]     + vv.x;
                        st.y = acc[mi][ni][2 * h + 1] + vv.y;
                        *(float2*)(srow + ni * 8) = st;
                    }
                }
                __syncthreads();
                // cooperative coalesced store: each warp 4 rows, 4 passes over cols
#pragma unroll
                for (int p = 0; p < 4; p++) {
                    int Rp = w * 4 + (lane >> 3);            // 0..31
                    int c4 = (lane & 7) + p * 8;             // float4 col 0..31
                    float4 val = *(const float4*)(stage + Rp * STP + c4 * 4);
                    int grow = r0 + (Rp >> 3) * 32 + mi * 16 + h * 8 + (Rp & 7);
                    *(float4*)(out + (size_t)grow * COUT + nt * 128 + c4 * 4) = val;
                }
                __syncthreads();
            }
        }
    }
}

// ---------------------------------------------------------------------------
extern "C" void kernel_launch(void* const* d_in, const int* in_sizes, int n_in,
                              void* d_out, int out_size) {
    const float* x  = (const float*)d_in[0];   // (8,256,256,64)
    const float* w1 = (const float*)d_in[1];   // (256,64)
    const float* b1 = (const float*)d_in[2];   // (256,)
    const float* w2 = (const float*)d_in[3];   // (256,320)
    float* out = (float*)d_out;                // (8,256,256,256)

    dim3 g1(2, BN_TOT);
    k1_mma_max<<<g1, 256>>>(x, w1, b1, w2);

    k2_v<<<BN_TOT / 4, 256>>>();

    dim3 g3(2, BN_TOT);
    k3_mma_out<<<g3, 256>>>(x, w2, out);
}

// round 13
// speedup vs baseline: 1.0510x; 1.0510x over previous
#include <cuda_runtime.h>
#include <cuda_fp16.h>
#include <cstdint>

#define BN_TOT 2048
#define M_DIM  256
#define CIN    64
#define CMID   256
#define COUT   256
#define W2P    320
#define AP     72          // fp16 smem pitch (144B rows), verified round 4
#define SP     72          // epilogue stage pitch in floats (bank-conflict-free, see notes)

// device scratch (zero-alloc rule)
__device__ float  g_zmax[BN_TOT * CMID];   // 2 MB, final max(+bias)
__device__ float  g_v[BN_TOT * COUT];      // 2 MB
__device__ __half g_w2bT[256 * 256];       // w2 cols 64..319 TRANSPOSED [d][o], fp16

// ---------------- PTX helpers ----------------
__device__ __forceinline__ unsigned smem_u32(const void* p) {
    return (unsigned)__cvta_generic_to_shared(p);
}
__device__ __forceinline__ void ldm4(unsigned r[4], unsigned addr) {
    asm volatile("ldmatrix.sync.aligned.m8n8.x4.shared.b16 {%0,%1,%2,%3}, [%4];"
                 : "=r"(r[0]), "=r"(r[1]), "=r"(r[2]), "=r"(r[3]) : "r"(addr));
}
__device__ __forceinline__ void mma_f16(float c[4], const unsigned a[4], const unsigned b[2]) {
    asm volatile("mma.sync.aligned.m16n8k16.row.col.f32.f16.f16.f32 "
                 "{%0,%1,%2,%3}, {%4,%5,%6,%7}, {%8,%9}, {%0,%1,%2,%3};"
                 : "+f"(c[0]), "+f"(c[1]), "+f"(c[2]), "+f"(c[3])
                 : "r"(a[0]), "r"(a[1]), "r"(a[2]), "r"(a[3]), "r"(b[0]), "r"(b[1]));
}

// ---------------------------------------------------------------------------
// Round-4 verified loader: 128 rows x 64 fp32 -> fp16 smem pitch AP
// ---------------------------------------------------------------------------
__device__ __forceinline__ void load_conv(__half* sm, const float* __restrict__ g,
                                          int row0, int pitch, int tid) {
#pragma unroll
    for (int it = 0; it < 4; it++) {
        int idx = it * 256 + tid;          // 0..1023
        int row = idx >> 3, q = idx & 7;
        const float* p = g + (size_t)(row0 + row) * pitch + q * 8;
        float4 v0 = *(const float4*)p;
        float4 v1 = *(const float4*)(p + 4);
        __half2 h0 = __halves2half2(__float2half_rn(v0.x), __float2half_rn(v0.y));
        __half2 h1 = __halves2half2(__float2half_rn(v0.z), __float2half_rn(v0.w));
        __half2 h2 = __halves2half2(__float2half_rn(v1.x), __float2half_rn(v1.y));
        __half2 h3 = __halves2half2(__float2half_rn(v1.z), __float2half_rn(v1.w));
        uint4 u;
        u.x = *(unsigned*)&h0; u.y = *(unsigned*)&h1;
        u.z = *(unsigned*)&h2; u.w = *(unsigned*)&h3;
        *(uint4*)(sm + row * AP + q * 8) = u;
    }
}

// ---------------------------------------------------------------------------
// Round-4 verified MMA core: 128x128x64, warp tile 32m x 64n
// ---------------------------------------------------------------------------
__device__ __forceinline__ void mma_core(float acc[2][8][4],
                                         const __half* sA, const __half* sB,
                                         int warp_m, int warp_n, int lane) {
    const int lrow = lane & 15, lkh = (lane >> 4) * 8;
#pragma unroll
    for (int ks = 0; ks < 64; ks += 16) {
        unsigned af[2][4];
#pragma unroll
        for (int mi = 0; mi < 2; mi++)
            ldm4(af[mi], smem_u32(sA + (warp_m * 32 + mi * 16 + lrow) * AP + ks + lkh));
        unsigned bf[8][2];
#pragma unroll
        for (int np = 0; np < 4; np++) {
            unsigned t[4];
            ldm4(t, smem_u32(sB + (warp_n * 64 + np * 16 + lrow) * AP + ks + lkh));
            bf[2*np][0]   = t[0]; bf[2*np+1][0] = t[1];
            bf[2*np][1]   = t[2]; bf[2*np+1][1] = t[3];
        }
#pragma unroll
        for (int mi = 0; mi < 2; mi++)
#pragma unroll
            for (int ni = 0; ni < 8; ni++)
                mma_f16(acc[mi][ni], af[mi], bf[ni]);
    }
}

// ---------------------------------------------------------------------------
// K1 (round-12 measured, 86.0us): grid(2 dt, BN). z = x @ w1^T,
// max over 256 m, + bias -> g_zmax. Folded w2b prep.
// ---------------------------------------------------------------------------
__global__ void __launch_bounds__(256)
k1_mma_max(const float* __restrict__ x, const float* __restrict__ w1,
           const float* __restrict__ b1, const float* __restrict__ w2)
{
    __shared__ __align__(16) __half sA[128 * AP];
    __shared__ __align__(16) __half sB[128 * AP];
    __shared__ float smax[4][128];

    const int tid = threadIdx.x;
    const int lane = tid & 31, w = tid >> 5;
    const int warp_m = w >> 1, warp_n = w & 1;
    const int dt = blockIdx.x, bn = blockIdx.y;

    smax[tid >> 7][tid & 127] = -3.4e38f;
    smax[2 + (tid >> 7)][tid & 127] = -3.4e38f;

    load_conv(sB, w1, dt * 128, CIN, tid);

    // folded prep: first 64 bn-CTAs of dt==0 build g_w2bT (K2 runs after K1)
    if (dt == 0 && bn < 64) {
#pragma unroll
        for (int it = 0; it < 4; it++) {
            int j = bn * 1024 + it * 256 + tid;   // 0..65535
            int o = j & 255, d = j >> 8;
            g_w2bT[d * 256 + o] = __float2half_rn(w2[(size_t)o * W2P + CIN + d]);
        }
    }

#pragma unroll
    for (int mt = 0; mt < 2; mt++) {
        __syncthreads();
        load_conv(sA, x, bn * 256 + mt * 128, CIN, tid);
        __syncthreads();

        float acc[2][8][4];
#pragma unroll
        for (int mi = 0; mi < 2; mi++)
#pragma unroll
            for (int ni = 0; ni < 8; ni++)
#pragma unroll
                for (int c = 0; c < 4; c++) acc[mi][ni][c] = 0.f;

        mma_core(acc, sA, sB, warp_m, warp_n, lane);

#pragma unroll
        for (int ni = 0; ni < 8; ni++) {
            float m0 = fmaxf(fmaxf(acc[0][ni][0], acc[0][ni][2]),
                             fmaxf(acc[1][ni][0], acc[1][ni][2]));
            float m1 = fmaxf(fmaxf(acc[0][ni][1], acc[0][ni][3]),
                             fmaxf(acc[1][ni][1], acc[1][ni][3]));
#pragma unroll
            for (int off = 4; off < 32; off <<= 1) {
                m0 = fmaxf(m0, __shfl_xor_sync(0xffffffffu, m0, off));
                m1 = fmaxf(m1, __shfl_xor_sync(0xffffffffu, m1, off));
            }
            if (lane < 4) {
                int col = warp_n * 64 + ni * 8 + lane * 2;
                smax[warp_m][col]     = fmaxf(smax[warp_m][col], m0);
                smax[warp_m][col + 1] = fmaxf(smax[warp_m][col + 1], m1);
            }
        }
    }

    __syncthreads();
    if (tid < 128) {
        float m = fmaxf(fmaxf(smax[0][tid], smax[1][tid]),
                        fmaxf(smax[2][tid], smax[3][tid]));
        g_zmax[(size_t)bn * CMID + dt * 128 + tid] = m + b1[dt * 128 + tid];
    }
}

// ---------------------------------------------------------------------------
// K2 (round-9 measured, ~8us): grid(BN/4). 4 bn rows x 256 outputs per CTA.
// ---------------------------------------------------------------------------
__global__ void __launch_bounds__(256)
k2_v()
{
    __shared__ float zs[4][256];
    const int tid = threadIdx.x;
    const int bn0 = blockIdx.x * 4;

#pragma unroll
    for (int i = 0; i < 4; i++)
        zs[i][tid] = g_zmax[(size_t)(bn0 + i) * CMID + tid];
    __syncthreads();

    float a0 = 0.f, a1 = 0.f, a2 = 0.f, a3 = 0.f;
    const __half* wp = g_w2bT + tid;
#pragma unroll 4
    for (int d = 0; d < 256; d += 2) {
        float w0 = __half2float(wp[(size_t)d * 256]);
        float w1v = __half2float(wp[(size_t)(d + 1) * 256]);
        float2 z0 = *(const float2*)&zs[0][d];
        float2 z1 = *(const float2*)&zs[1][d];
        float2 z2 = *(const float2*)&zs[2][d];
        float2 z3 = *(const float2*)&zs[3][d];
        a0 = fmaf(z0.x, w0, a0); a0 = fmaf(z0.y, w1v, a0);
        a1 = fmaf(z1.x, w0, a1); a1 = fmaf(z1.y, w1v, a1);
        a2 = fmaf(z2.x, w0, a2); a2 = fmaf(z2.y, w1v, a2);
        a3 = fmaf(z3.x, w0, a3); a3 = fmaf(z3.y, w1v, a3);
    }
    g_v[(size_t)(bn0 + 0) * COUT + tid] = a0;
    g_v[(size_t)(bn0 + 1) * COUT + tid] = a1;
    g_v[(size_t)(bn0 + 2) * COUT + tid] = a2;
    g_v[(size_t)(bn0 + 3) * COUT + tid] = a3;
}

// ---------------------------------------------------------------------------
// K3: grid(2 nt, BN). out = x @ w2a^T + v, 2 row phases.
// Barrier-free per-warp staged epilogue: STS.64 (conflict-free, pitch 72) ->
// LDS.128 -> fully-coalesced STG.128 (4 lines/instr vs 8 for the old STG.64).
// Dynamic smem: sA 18432 | sB 18432 | sv 512 | 8 warp stages 16x72 f32.
// ---------------------------------------------------------------------------
#define K3_SA    0
#define K3_SB    18432
#define K3_SV    36864
#define K3_STG   37376
#define K3_SMEM  (37376 + 8 * 16 * SP * 4)   // 74240 B

__global__ void __launch_bounds__(256)
k3_mma_out(const float* __restrict__ x, const float* __restrict__ w2,
           float* __restrict__ out)
{
    extern __shared__ __align__(16) char smem[];
    __half* sA = (__half*)(smem + K3_SA);
    __half* sB = (__half*)(smem + K3_SB);
    float*  sv = (float*)(smem + K3_SV);

    const int tid = threadIdx.x;
    const int lane = tid & 31, w = tid >> 5;
    const int warp_m = w >> 1, warp_n = w & 1;
    const int nt = blockIdx.x, bn = blockIdx.y;

    float* stg = (float*)(smem + K3_STG) + w * (16 * SP);   // private per-warp

    if (tid < 128) sv[tid] = g_v[(size_t)bn * COUT + nt * 128 + tid];

    load_conv(sB, w2, nt * 128, W2P, tid);   // w2a = first 64 cols of pitch-320 rows

#pragma unroll
    for (int rt = 0; rt < 2; rt++) {
        const int r0 = bn * 256 + rt * 128;
        __syncthreads();
        load_conv(sA, x, r0, CIN, tid);
        __syncthreads();

        float acc[2][8][4];
#pragma unroll
        for (int mi = 0; mi < 2; mi++)
#pragma unroll
            for (int ni = 0; ni < 8; ni++)
#pragma unroll
                for (int c = 0; c < 4; c++) acc[mi][ni][c] = 0.f;

        mma_core(acc, sA, sB, warp_m, warp_n, lane);

        // per-warp staged epilogue (no CTA barriers)
#pragma unroll
        for (int mi = 0; mi < 2; mi++) {
            const int rloc = lane >> 2;           // 0..7
            const int cloc = (lane & 3) * 2;      // 0,2,4,6
#pragma unroll
            for (int ni = 0; ni < 8; ni++) {
                float2 vv = *(const float2*)(sv + warp_n * 64 + ni * 8 + cloc);
                float2 s0, s1;
                s0.x = acc[mi][ni][0] + vv.x; s0.y = acc[mi][ni][1] + vv.y;
                s1.x = acc[mi][ni][2] + vv.x; s1.y = acc[mi][ni][3] + vv.y;
                *(float2*)(stg + rloc * SP + ni * 8 + cloc)       = s0;
                *(float2*)(stg + (rloc + 8) * SP + ni * 8 + cloc) = s1;
            }
            __syncwarp();
            // coalesced store: iter p stores rows 2p, 2p+1 (64 cols each)
            const int rr_half = lane >> 4;        // 0..1
            const int c4 = lane & 15;             // float4 col 0..15
#pragma unroll
            for (int p = 0; p < 8; p++) {
                int rr = 2 * p + rr_half;
                float4 val = *(const float4*)(stg + rr * SP + c4 * 4);
                int grow = r0 + warp_m * 32 + mi * 16 + rr;
                *(float4*)(out + (size_t)grow * COUT + nt * 128 + warp_n * 64 + c4 * 4) = val;
            }
            __syncwarp();
        }
    }
}

// ---------------------------------------------------------------------------
extern "C" void kernel_launch(void* const* d_in, const int* in_sizes, int n_in,
                              void* d_out, int out_size) {
    const float* x  = (const float*)d_in[0];   // (8,256,256,64)
    const float* w1 = (const float*)d_in[1];   // (256,64)
    const float* b1 = (const float*)d_in[2];   // (256,)
    const float* w2 = (const float*)d_in[3];   // (256,320)
    float* out = (float*)d_out;                // (8,256,256,256)

    static bool attr_set = false;
    if (!attr_set) {
        cudaFuncSetAttribute(k3_mma_out, cudaFuncAttributeMaxDynamicSharedMemorySize, K3_SMEM);
        attr_set = true;
    }

    dim3 g1(2, BN_TOT);
    k1_mma_max<<<g1, 256>>>(x, w1, b1, w2);

    k2_v<<<BN_TOT / 4, 256>>>();

    dim3 g3(2, BN_TOT);
    k3_mma_out<<<g3, 256, K3_SMEM>>>(x, w2, out);
}

// round 14
// speedup vs baseline: 1.1630x; 1.1065x over previous
#include <cuda_runtime.h>
#include <cuda_fp16.h>
#include <cstdint>

#define BN_TOT 2048
#define M_DIM  256
#define CIN    64
#define CMID   256
#define COUT   256
#define W2P    320
#define AP     72          // fp16 smem pitch (144B rows), verified round 4

// device scratch (zero-alloc rule; zero-initialized at module load)
__device__ float g_zmax[BN_TOT * CMID];   // 2 MB, final max(+bias)
__device__ float g_v[BN_TOT * COUT];      // 2 MB
__device__ int   g_cnt[BN_TOT / 8];       // per-group arrival counters (self-resetting)

// ---------------- PTX helpers ----------------
__device__ __forceinline__ unsigned smem_u32(const void* p) {
    return (unsigned)__cvta_generic_to_shared(p);
}
__device__ __forceinline__ void ldm4(unsigned r[4], unsigned addr) {
    asm volatile("ldmatrix.sync.aligned.m8n8.x4.shared.b16 {%0,%1,%2,%3}, [%4];"
                 : "=r"(r[0]), "=r"(r[1]), "=r"(r[2]), "=r"(r[3]) : "r"(addr));
}
__device__ __forceinline__ void mma_f16(float c[4], const unsigned a[4], const unsigned b[2]) {
    asm volatile("mma.sync.aligned.m16n8k16.row.col.f32.f16.f16.f32 "
                 "{%0,%1,%2,%3}, {%4,%5,%6,%7}, {%8,%9}, {%0,%1,%2,%3};"
                 : "+f"(c[0]), "+f"(c[1]), "+f"(c[2]), "+f"(c[3])
                 : "r"(a[0]), "r"(a[1]), "r"(a[2]), "r"(a[3]), "r"(b[0]), "r"(b[1]));
}

// ---------------------------------------------------------------------------
// Round-4 verified loader: 128 rows x 64 fp32 -> fp16 smem pitch AP
// ---------------------------------------------------------------------------
__device__ __forceinline__ void load_conv(__half* sm, const float* __restrict__ g,
                                          int row0, int pitch, int tid) {
#pragma unroll
    for (int it = 0; it < 4; it++) {
        int idx = it * 256 + tid;          // 0..1023
        int row = idx >> 3, q = idx & 7;
        const float* p = g + (size_t)(row0 + row) * pitch + q * 8;
        float4 v0 = *(const float4*)p;
        float4 v1 = *(const float4*)(p + 4);
        __half2 h0 = __halves2half2(__float2half_rn(v0.x), __float2half_rn(v0.y));
        __half2 h1 = __halves2half2(__float2half_rn(v0.z), __float2half_rn(v0.w));
        __half2 h2 = __halves2half2(__float2half_rn(v1.x), __float2half_rn(v1.y));
        __half2 h3 = __halves2half2(__float2half_rn(v1.z), __float2half_rn(v1.w));
        uint4 u;
        u.x = *(unsigned*)&h0; u.y = *(unsigned*)&h1;
        u.z = *(unsigned*)&h2; u.w = *(unsigned*)&h3;
        *(uint4*)(sm + row * AP + q * 8) = u;
    }
}

// ---------------------------------------------------------------------------
// Round-4 verified MMA core: 128x128x64, warp tile 32m x 64n
// ---------------------------------------------------------------------------
__device__ __forceinline__ void mma_core(float acc[2][8][4],
                                         const __half* sA, const __half* sB,
                                         int warp_m, int warp_n, int lane) {
    const int lrow = lane & 15, lkh = (lane >> 4) * 8;
#pragma unroll
    for (int ks = 0; ks < 64; ks += 16) {
        unsigned af[2][4];
#pragma unroll
        for (int mi = 0; mi < 2; mi++)
            ldm4(af[mi], smem_u32(sA + (warp_m * 32 + mi * 16 + lrow) * AP + ks + lkh));
        unsigned bf[8][2];
#pragma unroll
        for (int np = 0; np < 4; np++) {
            unsigned t[4];
            ldm4(t, smem_u32(sB + (warp_n * 64 + np * 16 + lrow) * AP + ks + lkh));
            bf[2*np][0]   = t[0]; bf[2*np+1][0] = t[1];
            bf[2*np][1]   = t[2]; bf[2*np+1][1] = t[3];
        }
#pragma unroll
        for (int mi = 0; mi < 2; mi++)
#pragma unroll
            for (int ni = 0; ni < 8; ni++)
                mma_f16(acc[mi][ni], af[mi], bf[ni]);
    }
}

// ---------------------------------------------------------------------------
// K1 (round-4 core + elect-CTA v): grid(2 dt, BN). z = x @ w1^T,
// max over 256 m, + bias -> g_zmax. Last CTA of each 16-CTA bn-group
// (2 dt x 8 bn) computes v[8 bn] in fp32 using dead sA/sB smem.
// ---------------------------------------------------------------------------
__global__ void __launch_bounds__(256)
k1_mma_max(const float* __restrict__ x, const float* __restrict__ w1,
           const float* __restrict__ b1, const float* __restrict__ w2)
{
    __shared__ __align__(16) __half sA[128 * AP];
    __shared__ __align__(16) __half sB[128 * AP];
    __shared__ float smax[4][128];
    __shared__ int s_old;

    const int tid = threadIdx.x;
    const int lane = tid & 31, w = tid >> 5;
    const int warp_m = w >> 1, warp_n = w & 1;
    const int dt = blockIdx.x, bn = blockIdx.y;

    smax[tid >> 7][tid & 127] = -3.4e38f;
    smax[2 + (tid >> 7)][tid & 127] = -3.4e38f;

    load_conv(sB, w1, dt * 128, CIN, tid);

#pragma unroll
    for (int mt = 0; mt < 2; mt++) {
        __syncthreads();
        load_conv(sA, x, bn * 256 + mt * 128, CIN, tid);
        __syncthreads();

        float acc[2][8][4];
#pragma unroll
        for (int mi = 0; mi < 2; mi++)
#pragma unroll
            for (int ni = 0; ni < 8; ni++)
#pragma unroll
                for (int c = 0; c < 4; c++) acc[mi][ni][c] = 0.f;

        mma_core(acc, sA, sB, warp_m, warp_n, lane);

#pragma unroll
        for (int ni = 0; ni < 8; ni++) {
            float m0 = fmaxf(fmaxf(acc[0][ni][0], acc[0][ni][2]),
                             fmaxf(acc[1][ni][0], acc[1][ni][2]));
            float m1 = fmaxf(fmaxf(acc[0][ni][1], acc[0][ni][3]),
                             fmaxf(acc[1][ni][1], acc[1][ni][3]));
#pragma unroll
            for (int off = 4; off < 32; off <<= 1) {
                m0 = fmaxf(m0, __shfl_xor_sync(0xffffffffu, m0, off));
                m1 = fmaxf(m1, __shfl_xor_sync(0xffffffffu, m1, off));
            }
            if (lane < 4) {
                int col = warp_n * 64 + ni * 8 + lane * 2;
                smax[warp_m][col]     = fmaxf(smax[warp_m][col], m0);
                smax[warp_m][col + 1] = fmaxf(smax[warp_m][col + 1], m1);
            }
        }
    }

    __syncthreads();
    if (tid < 128) {
        float m = fmaxf(fmaxf(smax[0][tid], smax[1][tid]),
                        fmaxf(smax[2][tid], smax[3][tid]));
        g_zmax[(size_t)bn * CMID + dt * 128 + tid] = m + b1[dt * 128 + tid];
    }

    // ---- group arrival: release our zmax writes, count arrivals ----
    __threadfence();                 // release (writers ordered before atomic)
    __syncthreads();                 // all zmax STG issued before tid0 arrives
    const int grp = bn >> 3;
    if (tid == 0) s_old = atomicAdd(&g_cnt[grp], 1);
    __syncthreads();

    if (s_old == 15) {               // elect: all 16 group CTAs done
        __threadfence();             // acquire (see peers' zmax)

        float* zsm = (float*)sB;     // 8 x 256 f32 = 8 KB   (sB dead)
        float* wsm = (float*)sA;     // 16 x 257 f32 = 16.4KB (sA dead)
        const int bn0 = grp << 3;

        // stage zmax group, coalesced
        for (int i = tid; i < 2048; i += 256)
            zsm[i] = g_zmax[(size_t)(bn0 + (i >> 8)) * CMID + (i & 255)];

        float vac[8];
#pragma unroll
        for (int r = 0; r < 8; r++) vac[r] = 0.f;

        const int o = tid;
        for (int c = 0; c < 16; c++) {           // 16 chunks of 16 d
            __syncthreads();
            // stage w2b chunk fp32, coalesced float4, transpose into wsm[d][o]
#pragma unroll
            for (int it = 0; it < 4; it++) {
                int idx = it * 256 + tid;        // 0..1023
                int oo = idx >> 2, dq = (idx & 3) * 4;
                float4 wv = *(const float4*)(w2 + (size_t)oo * W2P + CIN + c * 16 + dq);
                wsm[(dq + 0) * 257 + oo] = wv.x;
                wsm[(dq + 1) * 257 + oo] = wv.y;
                wsm[(dq + 2) * 257 + oo] = wv.z;
                wsm[(dq + 3) * 257 + oo] = wv.w;
            }
            __syncthreads();
#pragma unroll
            for (int dd = 0; dd < 16; dd++) {
                float wv = wsm[dd * 257 + o];
                int d = c * 16 + dd;
#pragma unroll
                for (int r = 0; r < 8; r++)
                    vac[r] = fmaf(zsm[r * 256 + d], wv, vac[r]);
            }
        }
#pragma unroll
        for (int r = 0; r < 8; r++)
            g_v[(size_t)(bn0 + r) * COUT + o] = vac[r];

        if (tid == 0) g_cnt[grp] = 0;            // reset for next graph replay
    }
}

// ---------------------------------------------------------------------------
// K3 (exact round-4): grid(2 nt, BN). out = x @ w2a^T + v, 2 row phases.
// ---------------------------------------------------------------------------
__global__ void __launch_bounds__(256)
k3_mma_out(const float* __restrict__ x, const float* __restrict__ w2,
           float* __restrict__ out)
{
    __shared__ __align__(16) __half sA[128 * AP];
    __shared__ __align__(16) __half sB[128 * AP];
    __shared__ float sv[128];

    const int tid = threadIdx.x;
    const int lane = tid & 31, w = tid >> 5;
    const int warp_m = w >> 1, warp_n = w & 1;
    const int nt = blockIdx.x, bn = blockIdx.y;

    if (tid < 128) sv[tid] = g_v[(size_t)bn * COUT + nt * 128 + tid];

    load_conv(sB, w2, nt * 128, W2P, tid);   // w2a = first 64 cols of pitch-320 rows

#pragma unroll
    for (int rt = 0; rt < 2; rt++) {
        const int r0 = bn * 256 + rt * 128;
        __syncthreads();
        load_conv(sA, x, r0, CIN, tid);
        __syncthreads();

        float acc[2][8][4];
#pragma unroll
        for (int mi = 0; mi < 2; mi++)
#pragma unroll
            for (int ni = 0; ni < 8; ni++)
#pragma unroll
                for (int c = 0; c < 4; c++) acc[mi][ni][c] = 0.f;

        mma_core(acc, sA, sB, warp_m, warp_n, lane);

#pragma unroll
        for (int ni = 0; ni < 8; ni++) {
            int cfrag = warp_n * 64 + ni * 8 + (lane & 3) * 2;
            int col = nt * 128 + cfrag;
            float2 vv = *(const float2*)(sv + cfrag);
#pragma unroll
            for (int mi = 0; mi < 2; mi++) {
                int row = r0 + warp_m * 32 + mi * 16 + (lane >> 2);
                float2 o0v, o1v;
                o0v.x = acc[mi][ni][0] + vv.x; o0v.y = acc[mi][ni][1] + vv.y;
                o1v.x = acc[mi][ni][2] + vv.x; o1v.y = acc[mi][ni][3] + vv.y;
                *(float2*)(out + (size_t)row * COUT + col)       = o0v;
                *(float2*)(out + (size_t)(row + 8) * COUT + col) = o1v;
            }
        }
    }
}

// ---------------------------------------------------------------------------
extern "C" void kernel_launch(void* const* d_in, const int* in_sizes, int n_in,
                              void* d_out, int out_size) {
    const float* x  = (const float*)d_in[0];   // (8,256,256,64)
    const float* w1 = (const float*)d_in[1];   // (256,64)
    const float* b1 = (const float*)d_in[2];   // (256,)
    const float* w2 = (const float*)d_in[3];   // (256,320)
    float* out = (float*)d_out;                // (8,256,256,256)

    dim3 g1(2, BN_TOT);
    k1_mma_max<<<g1, 256>>>(x, w1, b1, w2);

    dim3 g3(2, BN_TOT);
    k3_mma_out<<<g3, 256>>>(x, w2, out);
}

// round 15
// speedup vs baseline: 1.1987x; 1.0307x over previous
#include <cuda_runtime.h>
#include <cuda_fp16.h>
#include <cstdint>

#define BN_TOT 2048
#define M_DIM  256
#define CIN    64
#define CMID   256
#define COUT   256
#define W2P    320
#define AP     72          // fp16 smem pitch (144B rows), verified round 4

// device scratch (zero-alloc rule)
__device__ float  g_vp[2 * BN_TOT * COUT];   // v partials per dt slab, 4 MB
__device__ __half g_w2bT[256 * 256];         // w2 cols 64..319 TRANSPOSED [d][o], fp16

// ---------------- PTX helpers ----------------
__device__ __forceinline__ unsigned smem_u32(const void* p) {
    return (unsigned)__cvta_generic_to_shared(p);
}
__device__ __forceinline__ void ldm4(unsigned r[4], unsigned addr) {
    asm volatile("ldmatrix.sync.aligned.m8n8.x4.shared.b16 {%0,%1,%2,%3}, [%4];"
                 : "=r"(r[0]), "=r"(r[1]), "=r"(r[2]), "=r"(r[3]) : "r"(addr));
}
__device__ __forceinline__ void mma_f16(float c[4], const unsigned a[4], const unsigned b[2]) {
    asm volatile("mma.sync.aligned.m16n8k16.row.col.f32.f16.f16.f32 "
                 "{%0,%1,%2,%3}, {%4,%5,%6,%7}, {%8,%9}, {%0,%1,%2,%3};"
                 : "+f"(c[0]), "+f"(c[1]), "+f"(c[2]), "+f"(c[3])
                 : "r"(a[0]), "r"(a[1]), "r"(a[2]), "r"(a[3]), "r"(b[0]), "r"(b[1]));
}

// ---------------------------------------------------------------------------
// Prep (round-8 measured, 4.3us): w2b -> transposed fp16 [d][o]
// ---------------------------------------------------------------------------
__global__ void prep_w2b(const float* __restrict__ w2) {
    int j = blockIdx.x * 256 + threadIdx.x;   // 0..65535
    int o = j & 255, d = j >> 8;              // write coalesced in o
    g_w2bT[d * 256 + o] = __float2half_rn(w2[(size_t)o * W2P + CIN + d]);
}

// ---------------------------------------------------------------------------
// Round-4 verified loader: 128 rows x 64 fp32 -> fp16 smem pitch AP
// ---------------------------------------------------------------------------
__device__ __forceinline__ void load_conv(__half* sm, const float* __restrict__ g,
                                          int row0, int pitch, int tid) {
#pragma unroll
    for (int it = 0; it < 4; it++) {
        int idx = it * 256 + tid;          // 0..1023
        int row = idx >> 3, q = idx & 7;
        const float* p = g + (size_t)(row0 + row) * pitch + q * 8;
        float4 v0 = *(const float4*)p;
        float4 v1 = *(const float4*)(p + 4);
        __half2 h0 = __halves2half2(__float2half_rn(v0.x), __float2half_rn(v0.y));
        __half2 h1 = __halves2half2(__float2half_rn(v0.z), __float2half_rn(v0.w));
        __half2 h2 = __halves2half2(__float2half_rn(v1.x), __float2half_rn(v1.y));
        __half2 h3 = __halves2half2(__float2half_rn(v1.z), __float2half_rn(v1.w));
        uint4 u;
        u.x = *(unsigned*)&h0; u.y = *(unsigned*)&h1;
        u.z = *(unsigned*)&h2; u.w = *(unsigned*)&h3;
        *(uint4*)(sm + row * AP + q * 8) = u;
    }
}

// ---------------------------------------------------------------------------
// Round-4 verified MMA core: 128x128x64, warp tile 32m x 64n
// ---------------------------------------------------------------------------
__device__ __forceinline__ void mma_core(float acc[2][8][4],
                                         const __half* sA, const __half* sB,
                                         int warp_m, int warp_n, int lane) {
    const int lrow = lane & 15, lkh = (lane >> 4) * 8;
#pragma unroll
    for (int ks = 0; ks < 64; ks += 16) {
        unsigned af[2][4];
#pragma unroll
        for (int mi = 0; mi < 2; mi++)
            ldm4(af[mi], smem_u32(sA + (warp_m * 32 + mi * 16 + lrow) * AP + ks + lkh));
        unsigned bf[8][2];
#pragma unroll
        for (int np = 0; np < 4; np++) {
            unsigned t[4];
            ldm4(t, smem_u32(sB + (warp_n * 64 + np * 16 + lrow) * AP + ks + lkh));
            bf[2*np][0]   = t[0]; bf[2*np+1][0] = t[1];
            bf[2*np][1]   = t[2]; bf[2*np+1][1] = t[3];
        }
#pragma unroll
        for (int mi = 0; mi < 2; mi++)
#pragma unroll
            for (int ni = 0; ni < 8; ni++)
                mma_f16(acc[mi][ni], af[mi], bf[ni]);
    }
}

// ---------------------------------------------------------------------------
// K1 (round-4 core + local v-partial): grid(2 dt, BN). z = x @ w1^T,
// max over 256 m, + bias -> zfin (smem only), then
// vp[dt][bn][o] = sum_{d in dt half} zfin[d] * w2b[o][d]   (fp16 w2bT, coalesced)
// No cross-CTA sync; g_zmax eliminated.
// ---------------------------------------------------------------------------
__global__ void __launch_bounds__(256)
k1_mma_max(const float* __restrict__ x, const float* __restrict__ w1,
           const float* __restrict__ b1)
{
    __shared__ __align__(16) __half sA[128 * AP];
    __shared__ __align__(16) __half sB[128 * AP];
    __shared__ float smax[4][128];

    const int tid = threadIdx.x;
    const int lane = tid & 31, w = tid >> 5;
    const int warp_m = w >> 1, warp_n = w & 1;
    const int dt = blockIdx.x, bn = blockIdx.y;

    smax[tid >> 7][tid & 127] = -3.4e38f;
    smax[2 + (tid >> 7)][tid & 127] = -3.4e38f;

    load_conv(sB, w1, dt * 128, CIN, tid);

#pragma unroll
    for (int mt = 0; mt < 2; mt++) {
        __syncthreads();
        load_conv(sA, x, bn * 256 + mt * 128, CIN, tid);
        __syncthreads();

        float acc[2][8][4];
#pragma unroll
        for (int mi = 0; mi < 2; mi++)
#pragma unroll
            for (int ni = 0; ni < 8; ni++)
#pragma unroll
                for (int c = 0; c < 4; c++) acc[mi][ni][c] = 0.f;

        mma_core(acc, sA, sB, warp_m, warp_n, lane);

#pragma unroll
        for (int ni = 0; ni < 8; ni++) {
            float m0 = fmaxf(fmaxf(acc[0][ni][0], acc[0][ni][2]),
                             fmaxf(acc[1][ni][0], acc[1][ni][2]));
            float m1 = fmaxf(fmaxf(acc[0][ni][1], acc[0][ni][3]),
                             fmaxf(acc[1][ni][1], acc[1][ni][3]));
#pragma unroll
            for (int off = 4; off < 32; off <<= 1) {
                m0 = fmaxf(m0, __shfl_xor_sync(0xffffffffu, m0, off));
                m1 = fmaxf(m1, __shfl_xor_sync(0xffffffffu, m1, off));
            }
            if (lane < 4) {
                int col = warp_n * 64 + ni * 8 + lane * 2;
                smax[warp_m][col]     = fmaxf(smax[warp_m][col], m0);
                smax[warp_m][col + 1] = fmaxf(smax[warp_m][col + 1], m1);
            }
        }
    }

    __syncthreads();
    // zfin (final max + bias) -> smax[0][*]; thread tid touches only column tid
    if (tid < 128) {
        float m = fmaxf(fmaxf(smax[0][tid], smax[1][tid]),
                        fmaxf(smax[2][tid], smax[3][tid]));
        smax[0][tid] = m + b1[dt * 128 + tid];
    }
    __syncthreads();

    // v-partial: thread = o; 128 coalesced fp16 loads from this dt's w2bT half
    {
        const float* zf = &smax[0][0];
        const __half* wp = g_w2bT + (size_t)(dt * 128) * 256 + tid;
        float a0 = 0.f, a1 = 0.f;
#pragma unroll 8
        for (int d = 0; d < 128; d += 2) {
            a0 = fmaf(zf[d],     __half2float(wp[(size_t)d * 256]),       a0);
            a1 = fmaf(zf[d + 1], __half2float(wp[(size_t)(d + 1) * 256]), a1);
        }
        g_vp[((size_t)dt * BN_TOT + bn) * COUT + tid] = a0 + a1;
    }
}

// ---------------------------------------------------------------------------
// K3 (round-4 core; sv = vp0 + vp1): grid(2 nt, BN).
// out = x @ w2a^T + v, 2 row phases.
// ---------------------------------------------------------------------------
__global__ void __launch_bounds__(256)
k3_mma_out(const float* __restrict__ x, const float* __restrict__ w2,
           float* __restrict__ out)
{
    __shared__ __align__(16) __half sA[128 * AP];
    __shared__ __align__(16) __half sB[128 * AP];
    __shared__ float sv[128];

    const int tid = threadIdx.x;
    const int lane = tid & 31, w = tid >> 5;
    const int warp_m = w >> 1, warp_n = w & 1;
    const int nt = blockIdx.x, bn = blockIdx.y;

    if (tid < 128) {
        size_t o = (size_t)bn * COUT + nt * 128 + tid;
        sv[tid] = g_vp[o] + g_vp[(size_t)BN_TOT * COUT + o];
    }

    load_conv(sB, w2, nt * 128, W2P, tid);   // w2a = first 64 cols of pitch-320 rows

#pragma unroll
    for (int rt = 0; rt < 2; rt++) {
        const int r0 = bn * 256 + rt * 128;
        __syncthreads();
        load_conv(sA, x, r0, CIN, tid);
        __syncthreads();

        float acc[2][8][4];
#pragma unroll
        for (int mi = 0; mi < 2; mi++)
#pragma unroll
            for (int ni = 0; ni < 8; ni++)
#pragma unroll
                for (int c = 0; c < 4; c++) acc[mi][ni][c] = 0.f;

        mma_core(acc, sA, sB, warp_m, warp_n, lane);

#pragma unroll
        for (int ni = 0; ni < 8; ni++) {
            int cfrag = warp_n * 64 + ni * 8 + (lane & 3) * 2;
            int col = nt * 128 + cfrag;
            float2 vv = *(const float2*)(sv + cfrag);
#pragma unroll
            for (int mi = 0; mi < 2; mi++) {
                int row = r0 + warp_m * 32 + mi * 16 + (lane >> 2);
                float2 o0v, o1v;
                o0v.x = acc[mi][ni][0] + vv.x; o0v.y = acc[mi][ni][1] + vv.y;
                o1v.x = acc[mi][ni][2] + vv.x; o1v.y = acc[mi][ni][3] + vv.y;
                *(float2*)(out + (size_t)row * COUT + col)       = o0v;
                *(float2*)(out + (size_t)(row + 8) * COUT + col) = o1v;
            }
        }
    }
}

// ---------------------------------------------------------------------------
extern "C" void kernel_launch(void* const* d_in, const int* in_sizes, int n_in,
                              void* d_out, int out_size) {
    const float* x  = (const float*)d_in[0];   // (8,256,256,64)
    const float* w1 = (const float*)d_in[1];   // (256,64)
    const float* b1 = (const float*)d_in[2];   // (256,)
    const float* w2 = (const float*)d_in[3];   // (256,320)
    float* out = (float*)d_out;                // (8,256,256,256)

    prep_w2b<<<256, 256>>>(w2);

    dim3 g1(2, BN_TOT);
    k1_mma_max<<<g1, 256>>>(x, w1, b1);

    dim3 g3(2, BN_TOT);
    k3_mma_out<<<g3, 256>>>(x, w2, out);
}

// round 16
// speedup vs baseline: 1.2398x; 1.0343x over previous
#include <cuda_runtime.h>
#include <cuda_fp16.h>
#include <cstdint>

#define BN_TOT 2048
#define M_DIM  256
#define CIN    64
#define CMID   256
#define COUT   256
#define W2P    320
#define K2P    65
#define AP     72          // fp16 smem pitch (144B rows), verified round 4

// device scratch (zero-alloc rule)
__device__ float g_zmax[BN_TOT * CMID];   // 2 MB, final max(+bias)
__device__ float g_v[BN_TOT * COUT];      // 2 MB

// ---------------- PTX helpers ----------------
__device__ __forceinline__ unsigned smem_u32(const void* p) {
    return (unsigned)__cvta_generic_to_shared(p);
}
__device__ __forceinline__ void ldm4(unsigned r[4], unsigned addr) {
    asm volatile("ldmatrix.sync.aligned.m8n8.x4.shared.b16 {%0,%1,%2,%3}, [%4];"
                 : "=r"(r[0]), "=r"(r[1]), "=r"(r[2]), "=r"(r[3]) : "r"(addr));
}
__device__ __forceinline__ void mma_f16(float c[4], const unsigned a[4], const unsigned b[2]) {
    asm volatile("mma.sync.aligned.m16n8k16.row.col.f32.f16.f16.f32 "
                 "{%0,%1,%2,%3}, {%4,%5,%6,%7}, {%8,%9}, {%0,%1,%2,%3};"
                 : "+f"(c[0]), "+f"(c[1]), "+f"(c[2]), "+f"(c[3])
                 : "r"(a[0]), "r"(a[1]), "r"(a[2]), "r"(a[3]), "r"(b[0]), "r"(b[1]));
}

// ---------------------------------------------------------------------------
// Round-4 verified loader: 128 rows x 64 fp32 -> fp16 smem pitch AP
// ---------------------------------------------------------------------------
__device__ __forceinline__ void load_conv(__half* sm, const float* __restrict__ g,
                                          int row0, int pitch, int tid) {
#pragma unroll
    for (int it = 0; it < 4; it++) {
        int idx = it * 256 + tid;          // 0..1023
        int row = idx >> 3, q = idx & 7;
        const float* p = g + (size_t)(row0 + row) * pitch + q * 8;
        float4 v0 = *(const float4*)p;
        float4 v1 = *(const float4*)(p + 4);
        __half2 h0 = __halves2half2(__float2half_rn(v0.x), __float2half_rn(v0.y));
        __half2 h1 = __halves2half2(__float2half_rn(v0.z), __float2half_rn(v0.w));
        __half2 h2 = __halves2half2(__float2half_rn(v1.x), __float2half_rn(v1.y));
        __half2 h3 = __halves2half2(__float2half_rn(v1.z), __float2half_rn(v1.w));
        uint4 u;
        u.x = *(unsigned*)&h0; u.y = *(unsigned*)&h1;
        u.z = *(unsigned*)&h2; u.w = *(unsigned*)&h3;
        *(uint4*)(sm + row * AP + q * 8) = u;
    }
}

// ---------------------------------------------------------------------------
// Round-4 verified MMA core: 128x128x64, warp tile 32m x 64n
// ---------------------------------------------------------------------------
__device__ __forceinline__ void mma_core(float acc[2][8][4],
                                         const __half* sA, const __half* sB,
                                         int warp_m, int warp_n, int lane) {
    const int lrow = lane & 15, lkh = (lane >> 4) * 8;
#pragma unroll
    for (int ks = 0; ks < 64; ks += 16) {
        unsigned af[2][4];
#pragma unroll
        for (int mi = 0; mi < 2; mi++)
            ldm4(af[mi], smem_u32(sA + (warp_m * 32 + mi * 16 + lrow) * AP + ks + lkh));
        unsigned bf[8][2];
#pragma unroll
        for (int np = 0; np < 4; np++) {
            unsigned t[4];
            ldm4(t, smem_u32(sB + (warp_n * 64 + np * 16 + lrow) * AP + ks + lkh));
            bf[2*np][0]   = t[0]; bf[2*np+1][0] = t[1];
            bf[2*np][1]   = t[2]; bf[2*np+1][1] = t[3];
        }
#pragma unroll
        for (int mi = 0; mi < 2; mi++)
#pragma unroll
            for (int ni = 0; ni < 8; ni++)
                mma_f16(acc[mi][ni], af[mi], bf[ni]);
    }
}

// ---------------------------------------------------------------------------
// K1 (verbatim round-4): grid(2 dt, BN). z = x @ w1^T, max over 256 m,
// + bias -> g_zmax
// ---------------------------------------------------------------------------
__global__ void __launch_bounds__(256)
k1_mma_max(const float* __restrict__ x, const float* __restrict__ w1,
           const float* __restrict__ b1)
{
    __shared__ __align__(16) __half sA[128 * AP];
    __shared__ __align__(16) __half sB[128 * AP];
    __shared__ float smax[4][128];

    const int tid = threadIdx.x;
    const int lane = tid & 31, w = tid >> 5;
    const int warp_m = w >> 1, warp_n = w & 1;
    const int dt = blockIdx.x, bn = blockIdx.y;

    smax[tid >> 7][tid & 127] = -3.4e38f;
    smax[2 + (tid >> 7)][tid & 127] = -3.4e38f;

    load_conv(sB, w1, dt * 128, CIN, tid);

#pragma unroll
    for (int mt = 0; mt < 2; mt++) {
        __syncthreads();
        load_conv(sA, x, bn * 256 + mt * 128, CIN, tid);
        __syncthreads();

        float acc[2][8][4];
#pragma unroll
        for (int mi = 0; mi < 2; mi++)
#pragma unroll
            for (int ni = 0; ni < 8; ni++)
#pragma unroll
                for (int c = 0; c < 4; c++) acc[mi][ni][c] = 0.f;

        mma_core(acc, sA, sB, warp_m, warp_n, lane);

#pragma unroll
        for (int ni = 0; ni < 8; ni++) {
            float m0 = fmaxf(fmaxf(acc[0][ni][0], acc[0][ni][2]),
                             fmaxf(acc[1][ni][0], acc[1][ni][2]));
            float m1 = fmaxf(fmaxf(acc[0][ni][1], acc[0][ni][3]),
                             fmaxf(acc[1][ni][1], acc[1][ni][3]));
#pragma unroll
            for (int off = 4; off < 32; off <<= 1) {
                m0 = fmaxf(m0, __shfl_xor_sync(0xffffffffu, m0, off));
                m1 = fmaxf(m1, __shfl_xor_sync(0xffffffffu, m1, off));
            }
            if (lane < 4) {
                int col = warp_n * 64 + ni * 8 + lane * 2;
                smax[warp_m][col]     = fmaxf(smax[warp_m][col], m0);
                smax[warp_m][col + 1] = fmaxf(smax[warp_m][col + 1], m1);
            }
        }
    }

    __syncthreads();
    if (tid < 128) {
        float m = fmaxf(fmaxf(smax[0][tid], smax[1][tid]),
                        fmaxf(smax[2][tid], smax[3][tid]));
        g_zmax[(size_t)bn * CMID + dt * 128 + tid] = m + b1[dt * 128 + tid];
    }
}

// ---------------------------------------------------------------------------
// K2 (verbatim round-4): v = zmax @ w2b^T, fp32 SIMT
// ---------------------------------------------------------------------------
__global__ __launch_bounds__(256)
void k2_vgemm(const float* __restrict__ w2)
{
    __shared__ float aT[32 * K2P];
    __shared__ float bT[32 * K2P];

    const int tid = threadIdx.x;
    const int tx = tid & 15, ty = tid >> 4;
    const int o0  = blockIdx.x * 64;
    const int bn0 = blockIdx.y * 64;

    float acc[4][4];
#pragma unroll
    for (int i = 0; i < 4; i++)
#pragma unroll
        for (int j = 0; j < 4; j++) acc[i][j] = 0.f;

    for (int kc = 0; kc < CMID; kc += 32) {
        __syncthreads();
#pragma unroll
        for (int it = 0; it < 8; it++) {
            int l = tid + it * 256;
            int r = l >> 5, k = l & 31;
            aT[k * K2P + r] = g_zmax[(size_t)(bn0 + r) * CMID + kc + k];
            bT[k * K2P + r] = w2[(size_t)(o0 + r) * W2P + CIN + kc + k];
        }
        __syncthreads();
#pragma unroll
        for (int k = 0; k < 32; k++) {
            float a[4], b[4];
#pragma unroll
            for (int i = 0; i < 4; i++) a[i] = aT[k * K2P + ty * 4 + i];
#pragma unroll
            for (int j = 0; j < 4; j++) b[j] = bT[k * K2P + tx * 4 + j];
#pragma unroll
            for (int i = 0; i < 4; i++)
#pragma unroll
                for (int j = 0; j < 4; j++)
                    acc[i][j] = fmaf(a[i], b[j], acc[i][j]);
        }
    }
#pragma unroll
    for (int i = 0; i < 4; i++)
#pragma unroll
        for (int j = 0; j < 4; j++)
            g_v[(size_t)(bn0 + ty * 4 + i) * COUT + o0 + tx * 4 + j] = acc[i][j];
}

// ---------------------------------------------------------------------------
// K3 (merged nt): grid(BN). sB holds ALL 256 w2a rows; per rt phase the
// x tile is loaded ONCE and used for both nt halves (halves K3 x traffic,
// halves CTA count). MMA core + epilogue byte-identical to round 4.
// ---------------------------------------------------------------------------
__global__ void __launch_bounds__(256)
k3_mma_out(const float* __restrict__ x, const float* __restrict__ w2,
           float* __restrict__ out)
{
    __shared__ __align__(16) __half sA[128 * AP];
    __shared__ __align__(16) __half sB[256 * AP];
    __shared__ float sv[256];

    const int tid = threadIdx.x;
    const int lane = tid & 31, w = tid >> 5;
    const int warp_m = w >> 1, warp_n = w & 1;
    const int bn = blockIdx.x;

    sv[tid] = g_v[(size_t)bn * COUT + tid];

    load_conv(sB,            w2, 0,   W2P, tid);   // w2a rows 0..127
    load_conv(sB + 128 * AP, w2, 128, W2P, tid);   // w2a rows 128..255

#pragma unroll
    for (int rt = 0; rt < 2; rt++) {
        const int r0 = bn * 256 + rt * 128;
        __syncthreads();
        load_conv(sA, x, r0, CIN, tid);
        __syncthreads();

#pragma unroll
        for (int nth = 0; nth < 2; nth++) {
            float acc[2][8][4];
#pragma unroll
            for (int mi = 0; mi < 2; mi++)
#pragma unroll
                for (int ni = 0; ni < 8; ni++)
#pragma unroll
                    for (int c = 0; c < 4; c++) acc[mi][ni][c] = 0.f;

            mma_core(acc, sA, sB + nth * 128 * AP, warp_m, warp_n, lane);

#pragma unroll
            for (int ni = 0; ni < 8; ni++) {
                int cfrag = warp_n * 64 + ni * 8 + (lane & 3) * 2;
                int col = nth * 128 + cfrag;
                float2 vv = *(const float2*)(sv + col);
#pragma unroll
                for (int mi = 0; mi < 2; mi++) {
                    int row = r0 + warp_m * 32 + mi * 16 + (lane >> 2);
                    float2 o0v, o1v;
                    o0v.x = acc[mi][ni][0] + vv.x; o0v.y = acc[mi][ni][1] + vv.y;
                    o1v.x = acc[mi][ni][2] + vv.x; o1v.y = acc[mi][ni][3] + vv.y;
                    *(float2*)(out + (size_t)row * COUT + col)       = o0v;
                    *(float2*)(out + (size_t)(row + 8) * COUT + col) = o1v;
                }
            }
        }
    }
}

// ---------------------------------------------------------------------------
extern "C" void kernel_launch(void* const* d_in, const int* in_sizes, int n_in,
                              void* d_out, int out_size) {
    const float* x  = (const float*)d_in[0];   // (8,256,256,64)
    const float* w1 = (const float*)d_in[1];   // (256,64)
    const float* b1 = (const float*)d_in[2];   // (256,)
    const float* w2 = (const float*)d_in[3];   // (256,320)
    float* out = (float*)d_out;                // (8,256,256,256)

    dim3 g1(2, BN_TOT);
    k1_mma_max<<<g1, 256>>>(x, w1, b1);

    dim3 g2(COUT / 64, BN_TOT / 64);
    k2_vgemm<<<g2, 256>>>(w2);

    k3_mma_out<<<BN_TOT, 256>>>(x, w2, out);
}